// round 15
// baseline (speedup 1.0000x reference)
#include <cuda_runtime.h>
#include <cuda_fp16.h>

typedef unsigned int u32;

#define BB 8192
#define TT 140
#define MROWS 64
#define THREADS 512

// smem byte offsets
// weights (fp16): 3 chunks x 8192B: W0 W1i W1h
#define OFF_W    0
// h0: [parity] = 2 x 8192B (fp16) ; h1 same
#define OFF_H0   24576
#define OFF_H1   (24576 + 16384)
#define OFF_YP   (OFF_H1 + 16384)          // ypart[parity][pair][32] = 1024B
#define OFF_MB   (OFF_YP + 1024)           // 4 pairs x {full0,full1,free0,free1} x 8B
#define SMEM_BYTES (OFF_MB + 128)

__device__ __forceinline__ u32 s2u(const void* p) {
    u32 a;
    asm("{ .reg .u64 t; cvta.to.shared.u64 t, %1; cvt.u32.u64 %0, t; }"
        : "=r"(a) : "l"(p));
    return a;
}
#define LDSM4(r0, r1, r2, r3, a)                                          \
    asm volatile("ldmatrix.sync.aligned.m8n8.x4.shared.b16 "              \
                 "{%0,%1,%2,%3}, [%4];"                                   \
                 : "=r"(r0), "=r"(r1), "=r"(r2), "=r"(r3) : "r"(a))

__device__ __forceinline__ void mma16816(float (&d)[4], u32 a0, u32 a1,
                                         u32 a2, u32 a3, u32 b0, u32 b1) {
    asm volatile(
        "mma.sync.aligned.m16n8k16.row.col.f32.f16.f16.f32 "
        "{%0,%1,%2,%3}, {%4,%5,%6,%7}, {%8,%9}, {%0,%1,%2,%3};"
        : "+f"(d[0]), "+f"(d[1]), "+f"(d[2]), "+f"(d[3])
        : "r"(a0), "r"(a1), "r"(a2), "r"(a3), "r"(b0), "r"(b1));
}
__device__ __forceinline__ u32 cvtpack16(float hi, float lo) {  // {lo, hi} f16x2
    u32 r;
    asm("cvt.rn.f16x2.f32 %0, %1, %2;" : "=r"(r) : "f"(hi), "f"(lo));
    return r;
}
__device__ __forceinline__ float fast_tanh(float x) {
    float e = __expf(2.0f * x);
    return 1.0f - __fdividef(2.0f, e + 1.0f);
}
__device__ __forceinline__ void mbar_wait(u32 addr, u32 ph) {
    asm volatile(
        "{\n\t.reg .pred P;\n\t"
        "W%=:\n\t"
        "mbarrier.try_wait.parity.shared.b64 P, [%0], %1;\n\t"
        "@!P bra W%=;\n\t}"
        :: "r"(addr), "r"(ph) : "memory");
}
#define MBAR_INIT(a, c) \
    asm volatile("mbarrier.init.shared.b64 [%0], %1;" :: "r"(a), "r"(c) : "memory")
#define MBAR_ARRIVE(a) \
    asm volatile("mbarrier.arrive.shared.b64 _, [%0];" :: "r"(a) : "memory")
#define PRODBAR(id) asm volatile("bar.sync %0, %1;" :: "r"(id), "r"(64) : "memory")
#define CONSBAR(id) asm volatile("bar.sync %0, %1;" :: "r"(id), "r"(64) : "memory")

__global__ void __launch_bounds__(THREADS, 1) rnn_kernel(
    const float* __restrict__ x, const float* __restrict__ h_state,
    const float* __restrict__ Wih0, const float* __restrict__ Whh0,
    const float* __restrict__ bih0, const float* __restrict__ bhh0,
    const float* __restrict__ Wih1, const float* __restrict__ Whh1,
    const float* __restrict__ bih1, const float* __restrict__ bhh1,
    const float* __restrict__ Wout, const float* __restrict__ bout,
    float* __restrict__ out) {
    extern __shared__ char smem[];
    const int tid  = threadIdx.x;
    const int lane = tid & 31;
    const int w    = tid >> 5;
    const int role = w >> 3;            // 0 = producer (layer 0), 1 = consumer (layer 1)
    const int hf   = (w >> 2) & 1;      // j-column half
    const int wi   = (role == 0) ? (w & 3) : ((w + 3) & 3);
    const int g    = lane >> 2;
    const int tg   = lane & 3;
    const int wr0  = wi * 16;
    const int row0 = blockIdx.x * MROWS;
    const int bidP = 1 + wi;            // producer-pair barrier (64)
    const int bidC = 5 + wi;            // consumer-pair barrier (64)
    const int BT   = BB * TT;

    // ---- prologue: weights -> fp16, SW128-swizzled [j][k] ----
    {
        const float* Ws[3] = {Whh0, Wih1, Whh1};
        for (int idx = tid; idx < 3 * 4096; idx += THREADS) {
            int m = idx >> 12, e = idx & 4095, j = e >> 6, k = e & 63;
            float v = Ws[m][j * 64 + k];
            int sw = j * 128 + ((k * 2) ^ ((j & 7) << 4));
            *(__half*)(smem + OFF_W + m * 8192 + sw) = __float2half_rn(v);
        }
    }
    // h_state -> parity-0 buffers (fp16)
    for (int idx = tid; idx < MROWS * 64; idx += THREADS) {
        int r = idx >> 6, k = idx & 63;
        int sw = r * 128 + ((k * 2) ^ ((r & 7) << 4));
        *(__half*)(smem + OFF_H0 + sw) = __float2half_rn(h_state[(row0 + r) * 64 + k]);
        *(__half*)(smem + OFF_H1 + sw) = __float2half_rn(h_state[BB * 64 + (row0 + r) * 64 + k]);
    }
    const u32 smu = s2u(smem);
    // mbarriers: pair pp at OFF_MB + pp*32: full0, full1, free0, free1
    if (tid == 0) {
#pragma unroll
        for (int pp = 0; pp < 4; ++pp) {
            MBAR_INIT(smu + OFF_MB + pp * 32,      64u);
            MBAR_INIT(smu + OFF_MB + pp * 32 + 8,  64u);
            MBAR_INIT(smu + OFF_MB + pp * 32 + 16, 64u);
            MBAR_INIT(smu + OFF_MB + pp * 32 + 24, 64u);
        }
    }
    // per-lane constants: cols j = hf*32 + nt*8 + tg*2, +1
    float2 wi2[4], b02[4], b12[4], wo2[4];
#pragma unroll
    for (int nt = 0; nt < 4; ++nt) {
        int j = hf * 32 + nt * 8 + tg * 2;
        wi2[nt] = make_float2(Wih0[j], Wih0[j + 1]);
        b02[nt] = make_float2(bih0[j] + bhh0[j], bih0[j + 1] + bhh0[j + 1]);
        b12[nt] = make_float2(bih1[j] + bhh1[j], bih1[j + 1] + bhh1[j + 1]);
        wo2[nt] = make_float2(Wout[j], Wout[j + 1]);
    }
    const float bo = bout[0];
    __syncthreads();

    const u32 mb = smu + OFF_MB + wi * 32;   // this pair's mbarriers
    // pre-arm free[0], free[1]: producer's first two waits pass immediately
    if (role == 1) {
        MBAR_ARRIVE(mb + 16);
        MBAR_ARRIVE(mb + 24);
    }

    const int q    = lane >> 3;
    const int arow = wr0 + ((q & 1) << 3) + (lane & 7);
    const u32 aco  = (u32)((q >> 1) << 4);
    const u32 swz  = (u32)((lane & 7) << 4);
    const u32 ab0  = smu + OFF_H0 + arow * 128;   // + parity*8192
    const u32 ab1  = smu + OFF_H1 + arow * 128;
    const int brl  = (((lane >> 4) & 1) << 3) + (lane & 7);
    const u32 bco  = (u32)(((lane >> 3) & 1) << 4);
    const u32 bbase = smu + OFF_W + brl * 128;
    u32 st0[4], st1[4];
#pragma unroll
    for (int nt = 0; nt < 4; ++nt) {
        u32 c = (u32)((hf * 64 + nt * 16 + tg * 4) ^ (g << 4));
        st0[nt] = smu + OFF_H0 + (wr0 + g) * 128 + c;
        st1[nt] = smu + OFF_H1 + (wr0 + g) * 128 + c;
    }
    float* hf0out = out + BT + (row0 + wr0 + g) * 64 + hf * 32;
    float* hf1out = hf0out + BB * 64;

    if (role == 0) {
        // ================= producer: layer 0, j-half hf =================
        u32 w0f[4][2][4];
#pragma unroll
        for (int kt = 0; kt < 4; ++kt) {
            u32 boff = ((u32)(kt << 5) | bco) ^ swz;
#pragma unroll
            for (int np = 0; np < 2; ++np) {
                u32 bb = bbase + (u32)((hf * 2 + np) * 2048) + boff;
                LDSM4(w0f[kt][np][0], w0f[kt][np][1], w0f[kt][np][2], w0f[kt][np][3], bb);
            }
        }
        const float* gxA = x + (row0 + wr0 + g) * TT;
        const float* gxB = gxA + 8 * TT;
        float xAn = gxA[0], xBn = gxB[0];
        for (int t = 0; t < TT; ++t) {
            const u32 rbo = (u32)(t & 1) * 8192u, wbo = rbo ^ 8192u;
            const u32 wb = (u32)((t + 1) & 1);
            const u32 ph = (u32)((t >> 1) & 1);
            float xA = xAn, xB = xBn;
            int tn = (t + 1 < TT) ? t + 1 : TT - 1;
            xAn = gxA[tn]; xBn = gxB[tn];

            float acc[4][4];
#pragma unroll
            for (int n = 0; n < 4; ++n)
#pragma unroll
                for (int i = 0; i < 4; ++i) acc[n][i] = 0.0f;
#pragma unroll
            for (int kt = 0; kt < 4; ++kt) {
                u32 aoff = (((u32)(kt << 5)) | aco) ^ swz;
                u32 aH0, aH1, aH2, aH3;
                LDSM4(aH0, aH1, aH2, aH3, ab0 + rbo + aoff);
#pragma unroll
                for (int np = 0; np < 2; ++np) {
                    mma16816(acc[2 * np],     aH0, aH1, aH2, aH3,
                             w0f[kt][np][0], w0f[kt][np][1]);
                    mma16816(acc[2 * np + 1], aH0, aH1, aH2, aH3,
                             w0f[kt][np][2], w0f[kt][np][3]);
                }
            }
            u32 hpA[4], hpB[4];
#pragma unroll
            for (int nt = 0; nt < 4; ++nt) {
                float vA0 = fast_tanh(acc[nt][0] + fmaf(xA, wi2[nt].x, b02[nt].x));
                float vA1 = fast_tanh(acc[nt][1] + fmaf(xA, wi2[nt].y, b02[nt].y));
                float vB0 = fast_tanh(acc[nt][2] + fmaf(xB, wi2[nt].x, b02[nt].x));
                float vB1 = fast_tanh(acc[nt][3] + fmaf(xB, wi2[nt].y, b02[nt].y));
                hpA[nt] = cvtpack16(vA1, vA0);
                hpB[nt] = cvtpack16(vB1, vB0);
                if (t == TT - 1) {   // fp32 h0 final
                    int j = nt * 8 + tg * 2;
                    hf0out[j]              = vA0;
                    hf0out[j + 1]          = vA1;
                    hf0out[8 * 64 + j]     = vB0;
                    hf0out[8 * 64 + j + 1] = vB1;
                }
            }
            mbar_wait(mb + 16 + wb * 8, ph);   // free[wb]: consumer done reading (t-2)
#pragma unroll
            for (int nt = 0; nt < 4; ++nt) {
                asm volatile("st.shared.b32 [%0], %1;" :: "r"(st0[nt] + wbo), "r"(hpA[nt]));
                asm volatile("st.shared.b32 [%0], %1;" :: "r"(st0[nt] + wbo + 1024), "r"(hpB[nt]));
            }
            MBAR_ARRIVE(mb + wb * 8);          // full[wb]: h0n(t) published
            PRODBAR(bidP);                     // cross-half h0 visibility for next MMA
        }
    } else {
        // ================= consumer: layer 1, j-half hf =================
        u32 whf[4][2][4];
#pragma unroll
        for (int kt = 0; kt < 4; ++kt) {
            u32 boff = ((u32)(kt << 5) | bco) ^ swz;
#pragma unroll
            for (int np = 0; np < 2; ++np) {
                u32 bb = bbase + (u32)((hf * 2 + np) * 2048) + boff + 16384;
                LDSM4(whf[kt][np][0], whf[kt][np][1], whf[kt][np][2], whf[kt][np][3], bb);
            }
        }
        float* outy = out + (row0 + wr0 + g) * TT;
        for (int t = 0; t < TT; ++t) {
            const u32 rbo1 = (u32)(t & 1) * 8192u, wbo1 = rbo1 ^ 8192u;
            const u32 wb = (u32)((t + 1) & 1);
            const u32 ph = (u32)((t >> 1) & 1);
            float acc[4][4];
#pragma unroll
            for (int n = 0; n < 4; ++n)
#pragma unroll
                for (int i = 0; i < 4; ++i) acc[n][i] = 0.0f;
            // part 1: Whh1 x h1(t-1) — consumer-private
#pragma unroll
            for (int kt = 0; kt < 4; ++kt) {
                u32 aoff = (((u32)(kt << 5)) | aco) ^ swz;
                u32 r0, r1, r2, r3;
                LDSM4(r0, r1, r2, r3, ab1 + rbo1 + aoff);
#pragma unroll
                for (int np = 0; np < 2; ++np) {
                    mma16816(acc[2 * np],     r0, r1, r2, r3,
                             whf[kt][np][0], whf[kt][np][1]);
                    mma16816(acc[2 * np + 1], r0, r1, r2, r3,
                             whf[kt][np][2], whf[kt][np][3]);
                }
            }
            mbar_wait(mb + wb * 8, ph);        // full[wb]: wait h0n(t)
            // part 2: Wih1 x h0n(t)
#pragma unroll
            for (int kt = 0; kt < 4; ++kt) {
                u32 kc = (u32)(kt << 5);
                u32 aoff = (kc | aco) ^ swz;
                u32 p0, p1, p2, p3;
                LDSM4(p0, p1, p2, p3, ab0 + wb * 8192u + aoff);
                u32 boff = (kc | bco) ^ swz;
#pragma unroll
                for (int np = 0; np < 2; ++np) {
                    u32 bb = bbase + (u32)((hf * 2 + np) * 2048) + boff;
                    u32 ih0, ih1, ih2, ih3;
                    LDSM4(ih0, ih1, ih2, ih3, bb + 8192);    // W1i (fp16)
                    mma16816(acc[2 * np],     p0, p1, p2, p3, ih0, ih1);
                    mma16816(acc[2 * np + 1], p0, p1, p2, p3, ih2, ih3);
                }
            }
            MBAR_ARRIVE(mb + 16 + wb * 8);     // free[wb]: done reading h0n(t)
            float ypA = 0.0f, ypB = 0.0f;
            u32 hpA[4], hpB[4];
#pragma unroll
            for (int nt = 0; nt < 4; ++nt) {
                float vA0 = fast_tanh(acc[nt][0] + b12[nt].x);
                float vA1 = fast_tanh(acc[nt][1] + b12[nt].y);
                float vB0 = fast_tanh(acc[nt][2] + b12[nt].x);
                float vB1 = fast_tanh(acc[nt][3] + b12[nt].y);
                ypA = fmaf(vA0, wo2[nt].x, ypA); ypA = fmaf(vA1, wo2[nt].y, ypA);
                ypB = fmaf(vB0, wo2[nt].x, ypB); ypB = fmaf(vB1, wo2[nt].y, ypB);
                hpA[nt] = cvtpack16(vA1, vA0);
                hpB[nt] = cvtpack16(vB1, vB0);
                if (t == TT - 1) {   // fp32 h1 final
                    int j = nt * 8 + tg * 2;
                    hf1out[j]              = vA0;
                    hf1out[j + 1]          = vA1;
                    hf1out[8 * 64 + j]     = vB0;
                    hf1out[8 * 64 + j + 1] = vB1;
                }
            }
#pragma unroll
            for (int nt = 0; nt < 4; ++nt) {
                asm volatile("st.shared.b32 [%0], %1;" :: "r"(st1[nt] + wbo1), "r"(hpA[nt]));
                asm volatile("st.shared.b32 [%0], %1;" :: "r"(st1[nt] + wbo1 + 1024), "r"(hpB[nt]));
            }
            // y partial: reduce over tg within warp, stash (parity-buffered)
            ypA += __shfl_xor_sync(0xFFFFFFFF, ypA, 1);
            ypA += __shfl_xor_sync(0xFFFFFFFF, ypA, 2);
            ypB += __shfl_xor_sync(0xFFFFFFFF, ypB, 1);
            ypB += __shfl_xor_sync(0xFFFFFFFF, ypB, 2);
            float* yp = (float*)(smem + OFF_YP) + ((t & 1) << 7) + wi * 32;
            if (tg == 0) {
                yp[hf * 16 + g]     = ypA;
                yp[hf * 16 + g + 8] = ypB;
            }
            CONSBAR(bidC);   // h1n halves + ypart visible to consumer pair
            if (hf == 0 && tg == 0) {
                outy[t]          = yp[g]     + yp[16 + g]     + bo;
                outy[8 * TT + t] = yp[g + 8] + yp[16 + g + 8] + bo;
            }
        }
    }
}

extern "C" void kernel_launch(void* const* d_in, const int* in_sizes, int n_in,
                              void* d_out, int out_size) {
    (void)in_sizes; (void)n_in; (void)out_size;
    const float* x    = (const float*)d_in[0];
    const float* hs   = (const float*)d_in[1];
    const float* Wih0 = (const float*)d_in[2];
    const float* Whh0 = (const float*)d_in[3];
    const float* bih0 = (const float*)d_in[4];
    const float* bhh0 = (const float*)d_in[5];
    const float* Wih1 = (const float*)d_in[6];
    const float* Whh1 = (const float*)d_in[7];
    const float* bih1 = (const float*)d_in[8];
    const float* bhh1 = (const float*)d_in[9];
    const float* Wout = (const float*)d_in[10];
    const float* bout = (const float*)d_in[11];
    float* out = (float*)d_out;

    cudaFuncSetAttribute(rnn_kernel, cudaFuncAttributeMaxDynamicSharedMemorySize,
                         SMEM_BYTES);
    rnn_kernel<<<BB / MROWS, THREADS, SMEM_BYTES>>>(
        x, hs, Wih0, Whh0, bih0, bhh0, Wih1, Whh1, bih1, bhh1, Wout, bout, out);
}

// round 16
// speedup vs baseline: 1.3774x; 1.3774x over previous
#include <cuda_runtime.h>
#include <cuda_fp16.h>

typedef unsigned int u32;

#define BB 8192
#define TT 140
#define MROWS 64
#define THREADS 512

// smem byte offsets
// weights (fp16): 3 chunks x 8192B: W0 W1i W1h
#define OFF_W    0
// h0: [parity] = 2 x 8192B (fp16) ; h1 same
#define OFF_H0   24576
#define OFF_H1   (24576 + 16384)
#define OFF_YP   (OFF_H1 + 16384)
#define SMEM_BYTES (OFF_YP + 512)

__device__ __forceinline__ u32 s2u(const void* p) {
    u32 a;
    asm("{ .reg .u64 t; cvta.to.shared.u64 t, %1; cvt.u32.u64 %0, t; }"
        : "=r"(a) : "l"(p));
    return a;
}
#define LDSM4(r0, r1, r2, r3, a)                                          \
    asm volatile("ldmatrix.sync.aligned.m8n8.x4.shared.b16 "              \
                 "{%0,%1,%2,%3}, [%4];"                                   \
                 : "=r"(r0), "=r"(r1), "=r"(r2), "=r"(r3) : "r"(a))

__device__ __forceinline__ void mma16816(float (&d)[4], u32 a0, u32 a1,
                                         u32 a2, u32 a3, u32 b0, u32 b1) {
    asm volatile(
        "mma.sync.aligned.m16n8k16.row.col.f32.f16.f16.f32 "
        "{%0,%1,%2,%3}, {%4,%5,%6,%7}, {%8,%9}, {%0,%1,%2,%3};"
        : "+f"(d[0]), "+f"(d[1]), "+f"(d[2]), "+f"(d[3])
        : "r"(a0), "r"(a1), "r"(a2), "r"(a3), "r"(b0), "r"(b1));
}
__device__ __forceinline__ u32 cvtpack16(float hi, float lo) {  // {lo, hi} f16x2
    u32 r;
    asm("cvt.rn.f16x2.f32 %0, %1, %2;" : "=r"(r) : "f"(hi), "f"(lo));
    return r;
}
__device__ __forceinline__ float fast_tanh(float x) {
    float r;
    asm("tanh.approx.f32 %0, %1;" : "=f"(r) : "f"(x));
    return r;
}
#define PAIRBAR(id) asm volatile("bar.sync %0, %1;" :: "r"(id), "r"(128) : "memory")
#define CONSBAR(id) asm volatile("bar.sync %0, %1;" :: "r"(id), "r"(64) : "memory")

__global__ void __launch_bounds__(THREADS, 1) rnn_kernel(
    const float* __restrict__ x, const float* __restrict__ h_state,
    const float* __restrict__ Wih0, const float* __restrict__ Whh0,
    const float* __restrict__ bih0, const float* __restrict__ bhh0,
    const float* __restrict__ Wih1, const float* __restrict__ Whh1,
    const float* __restrict__ bih1, const float* __restrict__ bhh1,
    const float* __restrict__ Wout, const float* __restrict__ bout,
    float* __restrict__ out) {
    extern __shared__ char smem[];
    const int tid  = threadIdx.x;
    const int lane = tid & 31;
    const int w    = tid >> 5;
    const int role = w >> 3;            // 0 = producer (layer 0), 1 = consumer (layer 1)
    const int hf   = (w >> 2) & 1;      // j-column half
    const int wi   = (role == 0) ? (w & 3) : ((w + 3) & 3);
    const int g    = lane >> 2;
    const int tg   = lane & 3;
    const int wr0  = wi * 16;
    const int row0 = blockIdx.x * MROWS;
    const int bidP = 1 + wi;
    const int bidC = 5 + wi;
    const int BT   = BB * TT;

    // ---- prologue: weights -> fp16, SW128-swizzled [j][k] ----
    {
        const float* Ws[3] = {Whh0, Wih1, Whh1};
        for (int idx = tid; idx < 3 * 4096; idx += THREADS) {
            int m = idx >> 12, e = idx & 4095, j = e >> 6, k = e & 63;
            float v = Ws[m][j * 64 + k];
            int sw = j * 128 + ((k * 2) ^ ((j & 7) << 4));
            *(__half*)(smem + OFF_W + m * 8192 + sw) = __float2half_rn(v);
        }
    }
    // h_state -> parity-0 buffers (fp16)
    for (int idx = tid; idx < MROWS * 64; idx += THREADS) {
        int r = idx >> 6, k = idx & 63;
        int sw = r * 128 + ((k * 2) ^ ((r & 7) << 4));
        *(__half*)(smem + OFF_H0 + sw) = __float2half_rn(h_state[(row0 + r) * 64 + k]);
        *(__half*)(smem + OFF_H1 + sw) = __float2half_rn(h_state[BB * 64 + (row0 + r) * 64 + k]);
    }
    // per-lane constants: cols j = hf*32 + nt*8 + tg*2, +1
    float2 wi2[4], b02[4], b12[4], wo2[4];
#pragma unroll
    for (int nt = 0; nt < 4; ++nt) {
        int j = hf * 32 + nt * 8 + tg * 2;
        wi2[nt] = make_float2(Wih0[j], Wih0[j + 1]);
        b02[nt] = make_float2(bih0[j] + bhh0[j], bih0[j + 1] + bhh0[j + 1]);
        b12[nt] = make_float2(bih1[j] + bhh1[j], bih1[j + 1] + bhh1[j + 1]);
        wo2[nt] = make_float2(Wout[j], Wout[j + 1]);
    }
    const float bo = bout[0];
    __syncthreads();

    const u32 smu = s2u(smem);
    const int q    = lane >> 3;
    const int arow = wr0 + ((q & 1) << 3) + (lane & 7);
    const u32 aco  = (u32)((q >> 1) << 4);
    const u32 swz  = (u32)((lane & 7) << 4);
    const u32 ab0  = smu + OFF_H0 + arow * 128;   // + parity*8192
    const u32 ab1  = smu + OFF_H1 + arow * 128;
    const int brl  = (((lane >> 4) & 1) << 3) + (lane & 7);
    const u32 bco  = (u32)(((lane >> 3) & 1) << 4);
    const u32 bbase = smu + OFF_W + brl * 128;
    u32 st0[4], st1[4];
#pragma unroll
    for (int nt = 0; nt < 4; ++nt) {
        u32 c = (u32)((hf * 64 + nt * 16 + tg * 4) ^ (g << 4));
        st0[nt] = smu + OFF_H0 + (wr0 + g) * 128 + c;
        st1[nt] = smu + OFF_H1 + (wr0 + g) * 128 + c;
    }
    float* yprt = (float*)(smem + OFF_YP) + wi * 32;
    float* hf0out = out + BT + (row0 + wr0 + g) * 64 + hf * 32;
    float* hf1out = hf0out + BB * 64;

    if (role == 0) {
        // ================= producer: layer 0, j-half hf =================
        u32 w0f[4][2][4];
#pragma unroll
        for (int kt = 0; kt < 4; ++kt) {
            u32 boff = ((u32)(kt << 5) | bco) ^ swz;
#pragma unroll
            for (int np = 0; np < 2; ++np) {
                u32 bb = bbase + (u32)((hf * 2 + np) * 2048) + boff;
                LDSM4(w0f[kt][np][0], w0f[kt][np][1], w0f[kt][np][2], w0f[kt][np][3], bb);
            }
        }
        const float* gxA = x + (row0 + wr0 + g) * TT;
        const float* gxB = gxA + 8 * TT;
        float xAn = gxA[0], xBn = gxB[0];
        u32 p = 0;
        for (int t = 0; t < TT; ++t) {
            const u32 rdo = p * 8192u, wro = rdo ^ 8192u;
            float xA = xAn, xB = xBn;
            int tn = (t + 1 < TT) ? t + 1 : TT - 1;
            xAn = gxA[tn]; xBn = gxB[tn];

            float acc[4][4];
#pragma unroll
            for (int n = 0; n < 4; ++n)
#pragma unroll
                for (int i = 0; i < 4; ++i) acc[n][i] = 0.0f;
#pragma unroll
            for (int kt = 0; kt < 4; ++kt) {
                u32 aoff = (((u32)(kt << 5)) | aco) ^ swz;
                u32 aH0, aH1, aH2, aH3;
                LDSM4(aH0, aH1, aH2, aH3, ab0 + rdo + aoff);
#pragma unroll
                for (int np = 0; np < 2; ++np) {
                    mma16816(acc[2 * np],     aH0, aH1, aH2, aH3,
                             w0f[kt][np][0], w0f[kt][np][1]);
                    mma16816(acc[2 * np + 1], aH0, aH1, aH2, aH3,
                             w0f[kt][np][2], w0f[kt][np][3]);
                }
            }
            u32 hpA[4], hpB[4];
#pragma unroll
            for (int nt = 0; nt < 4; ++nt) {
                float vA0 = fast_tanh(acc[nt][0] + fmaf(xA, wi2[nt].x, b02[nt].x));
                float vA1 = fast_tanh(acc[nt][1] + fmaf(xA, wi2[nt].y, b02[nt].y));
                float vB0 = fast_tanh(acc[nt][2] + fmaf(xB, wi2[nt].x, b02[nt].x));
                float vB1 = fast_tanh(acc[nt][3] + fmaf(xB, wi2[nt].y, b02[nt].y));
                hpA[nt] = cvtpack16(vA1, vA0);
                hpB[nt] = cvtpack16(vB1, vB0);
                if (t == TT - 1) {   // fp32 h0 final
                    int j = nt * 8 + tg * 2;
                    hf0out[j]              = vA0;
                    hf0out[j + 1]          = vA1;
                    hf0out[8 * 64 + j]     = vB0;
                    hf0out[8 * 64 + j + 1] = vB1;
                }
            }
#pragma unroll
            for (int nt = 0; nt < 4; ++nt) {
                asm volatile("st.shared.b32 [%0], %1;" :: "r"(st0[nt] + wro), "r"(hpA[nt]));
                asm volatile("st.shared.b32 [%0], %1;" :: "r"(st0[nt] + wro + 1024), "r"(hpB[nt]));
            }
            PAIRBAR(bidP);   // publish h0n(t) to pair
            p ^= 1;
        }
    } else {
        // ================= consumer: layer 1, j-half hf =================
        u32 whf[4][2][4];
#pragma unroll
        for (int kt = 0; kt < 4; ++kt) {
            u32 boff = ((u32)(kt << 5) | bco) ^ swz;
#pragma unroll
            for (int np = 0; np < 2; ++np) {
                u32 bb = bbase + (u32)((hf * 2 + np) * 2048) + boff + 16384;
                LDSM4(whf[kt][np][0], whf[kt][np][1], whf[kt][np][2], whf[kt][np][3], bb);
            }
        }
        float* outy = out + (row0 + wr0 + g) * TT;
        u32 p = 0;
        for (int t = 0; t < TT; ++t) {
            const u32 rdo = p * 8192u, wro = rdo ^ 8192u;
            float acc[4][4];
#pragma unroll
            for (int n = 0; n < 4; ++n)
#pragma unroll
                for (int i = 0; i < 4; ++i) acc[n][i] = 0.0f;
            // part 1 (pre-pair-barrier): Whh1 x h1(t-1)
#pragma unroll
            for (int kt = 0; kt < 4; ++kt) {
                u32 aoff = (((u32)(kt << 5)) | aco) ^ swz;
                u32 r0, r1, r2, r3;
                LDSM4(r0, r1, r2, r3, ab1 + rdo + aoff);
#pragma unroll
                for (int np = 0; np < 2; ++np) {
                    mma16816(acc[2 * np],     r0, r1, r2, r3,
                             whf[kt][np][0], whf[kt][np][1]);
                    mma16816(acc[2 * np + 1], r0, r1, r2, r3,
                             whf[kt][np][2], whf[kt][np][3]);
                }
            }
            PAIRBAR(bidP);   // wait for producers' h0n(t)
            // part 2: Wih1 x h0n(t)  (h0n lives at parity wro)
#pragma unroll
            for (int kt = 0; kt < 4; ++kt) {
                u32 kc = (u32)(kt << 5);
                u32 aoff = (kc | aco) ^ swz;
                u32 p0, p1, p2, p3;
                LDSM4(p0, p1, p2, p3, ab0 + wro + aoff);
                u32 boff = (kc | bco) ^ swz;
#pragma unroll
                for (int np = 0; np < 2; ++np) {
                    u32 bb = bbase + (u32)((hf * 2 + np) * 2048) + boff;
                    u32 ih0, ih1, ih2, ih3;
                    LDSM4(ih0, ih1, ih2, ih3, bb + 8192);    // W1i (fp16)
                    mma16816(acc[2 * np],     p0, p1, p2, p3, ih0, ih1);
                    mma16816(acc[2 * np + 1], p0, p1, p2, p3, ih2, ih3);
                }
            }
            float ypA = 0.0f, ypB = 0.0f;
            u32 hpA[4], hpB[4];
#pragma unroll
            for (int nt = 0; nt < 4; ++nt) {
                float vA0 = fast_tanh(acc[nt][0] + b12[nt].x);
                float vA1 = fast_tanh(acc[nt][1] + b12[nt].y);
                float vB0 = fast_tanh(acc[nt][2] + b12[nt].x);
                float vB1 = fast_tanh(acc[nt][3] + b12[nt].y);
                ypA = fmaf(vA0, wo2[nt].x, ypA); ypA = fmaf(vA1, wo2[nt].y, ypA);
                ypB = fmaf(vB0, wo2[nt].x, ypB); ypB = fmaf(vB1, wo2[nt].y, ypB);
                hpA[nt] = cvtpack16(vA1, vA0);
                hpB[nt] = cvtpack16(vB1, vB0);
                if (t == TT - 1) {   // fp32 h1 final
                    int j = nt * 8 + tg * 2;
                    hf1out[j]              = vA0;
                    hf1out[j + 1]          = vA1;
                    hf1out[8 * 64 + j]     = vB0;
                    hf1out[8 * 64 + j + 1] = vB1;
                }
            }
#pragma unroll
            for (int nt = 0; nt < 4; ++nt) {
                asm volatile("st.shared.b32 [%0], %1;" :: "r"(st1[nt] + wro), "r"(hpA[nt]));
                asm volatile("st.shared.b32 [%0], %1;" :: "r"(st1[nt] + wro + 1024), "r"(hpB[nt]));
            }
            // y partial: reduce over tg within warp, stash per half
            ypA += __shfl_xor_sync(0xFFFFFFFF, ypA, 1);
            ypA += __shfl_xor_sync(0xFFFFFFFF, ypA, 2);
            ypB += __shfl_xor_sync(0xFFFFFFFF, ypB, 1);
            ypB += __shfl_xor_sync(0xFFFFFFFF, ypB, 2);
            if (tg == 0) {
                yprt[hf * 16 + g]     = ypA;
                yprt[hf * 16 + g + 8] = ypB;
            }
            CONSBAR(bidC);   // h1n (both halves) + ypart visible to consumer pair
            if (hf == 0 && tg == 0) {
                outy[t]          = yprt[g]     + yprt[16 + g]     + bo;
                outy[8 * TT + t] = yprt[g + 8] + yprt[16 + g + 8] + bo;
            }
            p ^= 1;
        }
    }
}

extern "C" void kernel_launch(void* const* d_in, const int* in_sizes, int n_in,
                              void* d_out, int out_size) {
    (void)in_sizes; (void)n_in; (void)out_size;
    const float* x    = (const float*)d_in[0];
    const float* hs   = (const float*)d_in[1];
    const float* Wih0 = (const float*)d_in[2];
    const float* Whh0 = (const float*)d_in[3];
    const float* bih0 = (const float*)d_in[4];
    const float* bhh0 = (const float*)d_in[5];
    const float* Wih1 = (const float*)d_in[6];
    const float* Whh1 = (const float*)d_in[7];
    const float* bih1 = (const float*)d_in[8];
    const float* bhh1 = (const float*)d_in[9];
    const float* Wout = (const float*)d_in[10];
    const float* bout = (const float*)d_in[11];
    float* out = (float*)d_out;

    cudaFuncSetAttribute(rnn_kernel, cudaFuncAttributeMaxDynamicSharedMemorySize,
                         SMEM_BYTES);
    rnn_kernel<<<BB / MROWS, THREADS, SMEM_BYTES>>>(
        x, hs, Wih0, Whh0, bih0, bhh0, Wih1, Whh1, bih1, bhh1, Wout, bout, out);
}